// round 1
// baseline (speedup 1.0000x reference)
#include <cuda_runtime.h>
#include <cstdint>
#include <math.h>

#define B_  128
#define F_  1024
#define W_  32
#define H_  64
#define G_  256     // 4H
#define FC  16      // f-chunk size (keeps double-buffered smem under 48KB)

// Scratch for the input projection: Xproj[b][t][g]  (4 MB, device global per rules)
__device__ float g_xproj[B_ * W_ * G_];

__device__ __forceinline__ uint32_t smem_u32(const void* p) {
    return (uint32_t)__cvta_generic_to_shared(p);
}
__device__ __forceinline__ void cp_async16(uint32_t s, const void* g) {
    asm volatile("cp.async.cg.shared.global [%0], [%1], 16;" :: "r"(s), "l"(g));
}

// ---------------------------------------------------------------------------
// Kernel A: Xproj[b, t, g] = sum_f x[b, f, t] * Wx[f, g]
// One block per batch element b. Out tile: 32 (t) x 256 (g).
// Thread (tg = tid&31, ttg = tid>>5) owns t in {4*ttg..4*ttg+3}, g in {tg+32*i}.
// ---------------------------------------------------------------------------
extern "C" __global__ void __launch_bounds__(256)
xproj_kernel(const float* __restrict__ x, const float* __restrict__ Wx)
{
    // stage layout: [xs: FC*W_ floats | ws: FC*G_ floats], double-buffered
    constexpr int XS = FC * W_;          // 512 floats
    constexpr int WS = FC * G_;          // 4096 floats
    constexpr int STAGE = XS + WS;       // 4608 floats = 18 KB
    __shared__ float sm[2 * STAGE];      // 36 KB

    const int b   = blockIdx.x;
    const int tid = threadIdx.x;
    const int tg  = tid & 31;
    const int ttg = tid >> 5;

    const float* xb = x + (size_t)b * F_ * W_;

    float acc[4][8];
#pragma unroll
    for (int j = 0; j < 4; ++j)
#pragma unroll
        for (int i = 0; i < 8; ++i) acc[j][i] = 0.f;

    constexpr int NC = F_ / FC;          // 64 chunks

    auto load_chunk = [&](int c, int stage) {
        float* xs = sm + stage * STAGE;
        float* ws = xs + XS;
        // x chunk: 512 floats = 128 float4 (threads 0..127)
        if (tid < 128) {
            const float* src = xb + c * FC * W_;
            cp_async16(smem_u32(xs + tid * 4), src + tid * 4);
        }
        // w chunk: 4096 floats = 1024 float4, 4 per thread
        const float* wsrc = Wx + (size_t)c * FC * G_;
#pragma unroll
        for (int r = 0; r < 4; ++r) {
            int idx = (r * 256 + tid) * 4;
            cp_async16(smem_u32(ws + idx), wsrc + idx);
        }
    };

    load_chunk(0, 0);
    asm volatile("cp.async.commit_group;");

    for (int c = 0; c < NC; ++c) {
        if (c + 1 < NC) {
            load_chunk(c + 1, (c + 1) & 1);
            asm volatile("cp.async.commit_group;");
            asm volatile("cp.async.wait_group 1;");
        } else {
            asm volatile("cp.async.wait_group 0;");
        }
        __syncthreads();

        const float* xs = sm + (c & 1) * STAGE;
        const float* ws = xs + XS;
#pragma unroll 4
        for (int f = 0; f < FC; ++f) {
            float wv[8];
#pragma unroll
            for (int i = 0; i < 8; ++i) wv[i] = ws[f * G_ + tg + 32 * i];   // stride-1 across lanes
            float xv[4];
#pragma unroll
            for (int j = 0; j < 4; ++j) xv[j] = xs[f * W_ + 4 * ttg + j];   // broadcast within warp
#pragma unroll
            for (int j = 0; j < 4; ++j)
#pragma unroll
                for (int i = 0; i < 8; ++i)
                    acc[j][i] = fmaf(xv[j], wv[i], acc[j][i]);
        }
        __syncthreads();
    }

    float* outb = g_xproj + (size_t)b * W_ * G_;
#pragma unroll
    for (int j = 0; j < 4; ++j)
#pragma unroll
        for (int i = 0; i < 8; ++i)
            outb[(4 * ttg + j) * G_ + tg + 32 * i] = acc[j][i];
}

// ---------------------------------------------------------------------------
// Kernel B: LSTM recurrence, one block per batch element, 256 threads.
// Thread j owns gate column j (Wh[:,j] cached in 64 registers).
// Gate order (Keras): i | f | g | o ; output per step is the CELL state.
// ---------------------------------------------------------------------------
extern "C" __global__ void __launch_bounds__(256)
lstm_kernel(const float* __restrict__ Wh, const float* __restrict__ b_lstm,
            float* __restrict__ out)
{
    __shared__ float h_s[H_];
    __shared__ float g_s[G_];

    const int b = blockIdx.x;
    const int j = threadIdx.x;

    float whr[H_];
#pragma unroll
    for (int k = 0; k < H_; ++k) whr[k] = Wh[k * G_ + j];   // coalesced
    const float bj = b_lstm[j];

    if (j < H_) h_s[j] = 0.f;
    float cst = 0.f;
    __syncthreads();

    const float* xp = g_xproj + (size_t)b * W_ * G_;
    float*       ob = out     + (size_t)b * W_ * H_;

    for (int t = 0; t < W_; ++t) {
        float x0 = xp[t * G_ + j];            // independent of recurrence; overlaps dot
        float a0 = 0.f, a1 = 0.f, a2 = 0.f, a3 = 0.f;
#pragma unroll
        for (int k = 0; k < H_; k += 4) {
            a0 = fmaf(h_s[k + 0], whr[k + 0], a0);
            a1 = fmaf(h_s[k + 1], whr[k + 1], a1);
            a2 = fmaf(h_s[k + 2], whr[k + 2], a2);
            a3 = fmaf(h_s[k + 3], whr[k + 3], a3);
        }
        g_s[j] = ((a0 + a1) + (a2 + a3)) + x0 + bj;
        __syncthreads();

        if (j < H_) {
            float gi = g_s[j];
            float gf = g_s[H_ + j];
            float gg = g_s[2 * H_ + j];
            float go = g_s[3 * H_ + j];
            float si = 1.f / (1.f + expf(-gi));
            float sf = 1.f / (1.f + expf(-gf));
            float so = 1.f / (1.f + expf(-go));
            cst = sf * cst + si * tanhf(gg);
            h_s[j] = so * tanhf(cst);
            ob[t * H_ + j] = cst;             // reference emits the CELL state
        }
        __syncthreads();
    }
}

// ---------------------------------------------------------------------------
extern "C" void kernel_launch(void* const* d_in, const int* in_sizes, int n_in,
                              void* d_out, int out_size)
{
    const float* x      = (const float*)d_in[0];
    const float* Wx     = (const float*)d_in[6];
    const float* Wh     = (const float*)d_in[7];
    const float* b_lstm = (const float*)d_in[8];
    float*       out    = (float*)d_out;

    xproj_kernel<<<B_, 256>>>(x, Wx);
    lstm_kernel<<<B_, 256>>>(Wh, b_lstm, out);
}

// round 2
// speedup vs baseline: 1.4030x; 1.4030x over previous
#include <cuda_runtime.h>
#include <cstdint>
#include <math.h>

#define B_  128
#define F_  1024
#define W_  32
#define H_  64
#define G_  256          // 4H
#define FC  8            // f rows per half-chunk
#define NC  64           // (F_/2)/FC chunks
#define STAGE 4608       // floats/stage: 2*(FC*W_) + 2*(FC*G_) = 512 + 4096

using u64 = unsigned long long;

__device__ __forceinline__ u64 fma2(u64 a, u64 b, u64 c) {
    u64 d; asm("fma.rn.f32x2 %0, %1, %2, %3;" : "=l"(d) : "l"(a), "l"(b), "l"(c)); return d;
}
__device__ __forceinline__ u64 add2(u64 a, u64 b) {
    u64 d; asm("add.rn.f32x2 %0, %1, %2;" : "=l"(d) : "l"(a), "l"(b)); return d;
}
__device__ __forceinline__ u64 pack2(float lo, float hi) {
    u64 d;
    asm("mov.b64 %0, {%1, %2};" : "=l"(d)
        : "r"(__float_as_uint(lo)), "r"(__float_as_uint(hi)));
    return d;
}
__device__ __forceinline__ float2 unpack2(u64 a) {
    unsigned lo, hi; asm("mov.b64 {%0, %1}, %2;" : "=r"(lo), "=r"(hi) : "l"(a));
    return make_float2(__uint_as_float(lo), __uint_as_float(hi));
}
__device__ __forceinline__ uint32_t smem_u32(const void* p) {
    return (uint32_t)__cvta_generic_to_shared(p);
}
__device__ __forceinline__ void cp16(uint32_t s, const void* g) {
    asm volatile("cp.async.cg.shared.global [%0], [%1], 16;" :: "r"(s), "l"(g));
}

// ---------------------------------------------------------------------------
// Fused kernel. One block per batch element, 256 threads.
//
// Phase 1 (gate pre-activation GEMM): Xp[t, g] = sum_f x[b, f, t] * Wx[f, g]
//   Softmax over the size-1 axis in the reference is identically 1, so the
//   whole attention branch is dead code and x_tilde == x_t.
//   Warps 0-3 take f in [0,512), warps 4-7 take f in [512,1024) (split-K).
//   Warp wt (=w&3) owns t in [8wt, 8wt+8); lane owns g in {2*lane + 64*i}
//   as f32x2 pairs. 32 fma.rn.f32x2 per (thread, f). Result reduced into the
//   staging smem (reused as the 32KB gate tile).
//
// Phase 2 (LSTM recurrence, 32 serial steps):
//   lane l of warp w: gate q = l>>3, idx = 8w + (l&7), col = q*64 + idx.
//   dot(h, Wh[:,col]) as 32 fma.rn.f32x2 on broadcast LDS of h pairs.
//   Activation: one warp-uniform __expf path (sigmoid / tanh share form).
//   Gate exchange via shuffles; h double-buffered -> ONE barrier per step.
//   Output per step is the CELL state (reference's s/h swap).
// ---------------------------------------------------------------------------
extern "C" __global__ void __launch_bounds__(256, 1)
attn_rnn_fused(const float* __restrict__ x,  const float* __restrict__ Wx,
               const float* __restrict__ Wh, const float* __restrict__ b_lstm,
               float* __restrict__ out)
{
    __shared__ __align__(16) float smem[2 * STAGE];   // 36864 B; phase2: first 8192 floats = gate tile
    __shared__ __align__(16) float h_s[2][H_];

    const int b    = blockIdx.x;
    const int tid  = threadIdx.x;
    const int w    = tid >> 5;
    const int lane = tid & 31;
    const int half = w >> 2;      // split-K group
    const int wt   = w & 3;       // t-group

    const float* xb = x + (size_t)b * F_ * W_;

    // ---------------- Phase 1: GEMM ----------------
    u64 acc[8][4];
#pragma unroll
    for (int j = 0; j < 8; ++j)
#pragma unroll
        for (int i = 0; i < 4; ++i) acc[j][i] = 0ull;

    auto load_chunk = [&](int c, int s) {
        float* st = smem + s * STAGE;
        // x: 2 halves x FC x 32 = 512 floats (contiguous per half)
        if (tid < 128) {
            int t4  = tid * 4;
            int xh  = t4 >> 8;
            int rem = t4 & 255;
            cp16(smem_u32(st + xh * 256 + rem),
                 xb + (size_t)(xh * 512 + c * FC) * W_ + rem);
        }
        // w: 2 halves x FC x 256 = 4096 floats (contiguous per half)
        float* ws = st + 512;
#pragma unroll
        for (int r = 0; r < 4; ++r) {
            int i4  = (r * 256 + tid) * 4;
            int wh  = i4 >> 11;
            int rem = i4 & 2047;
            cp16(smem_u32(ws + wh * 2048 + rem),
                 Wx + (size_t)(wh * 512 + c * FC) * G_ + rem);
        }
    };

    load_chunk(0, 0);
    asm volatile("cp.async.commit_group;");

    for (int c = 0; c < NC; ++c) {
        if (c + 1 < NC) {
            load_chunk(c + 1, (c + 1) & 1);
            asm volatile("cp.async.commit_group;");
            asm volatile("cp.async.wait_group 1;");
        } else {
            asm volatile("cp.async.wait_group 0;");
        }
        __syncthreads();

        const float* st   = smem + (c & 1) * STAGE;
        const float* xs_h = st + half * 256;
        const float* ws_h = st + 512 + half * 2048;

#pragma unroll
        for (int f = 0; f < FC; ++f) {
            float4 xa = *(const float4*)(xs_h + f * W_ + 8 * wt);       // broadcast in warp
            float4 xc = *(const float4*)(xs_h + f * W_ + 8 * wt + 4);
            u64 xd[8];
            xd[0] = pack2(xa.x, xa.x); xd[1] = pack2(xa.y, xa.y);
            xd[2] = pack2(xa.z, xa.z); xd[3] = pack2(xa.w, xa.w);
            xd[4] = pack2(xc.x, xc.x); xd[5] = pack2(xc.y, xc.y);
            xd[6] = pack2(xc.z, xc.z); xd[7] = pack2(xc.w, xc.w);
            const u64* wp = (const u64*)(ws_h + f * G_);
#pragma unroll
            for (int i = 0; i < 4; ++i) {
                u64 wv = wp[lane + 32 * i];   // stride-8B across lanes: conflict-free
#pragma unroll
                for (int j = 0; j < 8; ++j)
                    acc[j][i] = fma2(xd[j], wv, acc[j][i]);
            }
        }
        __syncthreads();
    }

    // ---------------- split-K reduction into gate tile ----------------
    u64* xp64 = (u64*)smem;   // gate tile: [32 t][128 f32x2-pairs of g]
    if (half == 1) {
#pragma unroll
        for (int j = 0; j < 8; ++j)
#pragma unroll
            for (int i = 0; i < 4; ++i)
                xp64[(8 * wt + j) * 128 + lane + 32 * i] = acc[j][i];
    }
    __syncthreads();
    if (half == 0) {
#pragma unroll
        for (int j = 0; j < 8; ++j)
#pragma unroll
            for (int i = 0; i < 4; ++i) {
                int o = (8 * wt + j) * 128 + lane + 32 * i;
                xp64[o] = add2(xp64[o], acc[j][i]);
            }
    }

    // ---------------- Phase 2: LSTM recurrence ----------------
    const int q   = lane >> 3;
    const int r   = lane & 7;
    const int idx = 8 * w + r;
    const int col = q * 64 + idx;

    u64 whp[H_ / 2];
#pragma unroll
    for (int m = 0; m < H_ / 2; ++m)
        whp[m] = pack2(Wh[(2 * m) * G_ + col], Wh[(2 * m + 1) * G_ + col]);
    const float bj = b_lstm[col];

    if (tid < H_) h_s[0][tid] = 0.f;
    float c_st = 0.f;
    const float* xp = smem;
    float* ob = out + (size_t)b * W_ * H_;
    __syncthreads();

    int p = 0;
    for (int t = 0; t < W_; ++t) {
        const u64* hp = (const u64*)h_s[p];     // broadcast across lanes
        u64 a0 = 0ull, a1 = 0ull, a2 = 0ull, a3 = 0ull;
#pragma unroll
        for (int m = 0; m < H_ / 2; m += 4) {
            a0 = fma2(hp[m + 0], whp[m + 0], a0);
            a1 = fma2(hp[m + 1], whp[m + 1], a1);
            a2 = fma2(hp[m + 2], whp[m + 2], a2);
            a3 = fma2(hp[m + 3], whp[m + 3], a3);
        }
        float2 s2 = unpack2(add2(add2(a0, a1), add2(a2, a3)));
        float g = s2.x + s2.y + xp[t * G_ + col] + bj;

        // unified activation: q==2 -> tanh(g), else sigmoid(g)
        float sc  = (q == 2) ? -2.f : -1.f;
        float e   = __expf(sc * g);
        float num = (q == 2) ? (1.f - e) : 1.f;
        float act = __fdividef(num, 1.f + e);

        float ai = __shfl_sync(0xffffffffu, act, r);        // sigmoid(i)
        float af = __shfl_sync(0xffffffffu, act, 8 + r);    // sigmoid(f)
        float ag = __shfl_sync(0xffffffffu, act, 16 + r);   // tanh(g)
        float ao = __shfl_sync(0xffffffffu, act, 24 + r);   // sigmoid(o)

        c_st = fmaf(af, c_st, ai * ag);
        float e2 = __expf(-2.f * c_st);
        float th = __fdividef(1.f - e2, 1.f + e2);          // tanh(c_new)

        if (q == 0) {
            h_s[p ^ 1][idx] = ao * th;
            ob[t * H_ + idx] = c_st;                         // reference emits CELL state
        }
        p ^= 1;
        __syncthreads();
    }
}

// ---------------------------------------------------------------------------
extern "C" void kernel_launch(void* const* d_in, const int* in_sizes, int n_in,
                              void* d_out, int out_size)
{
    const float* x      = (const float*)d_in[0];
    const float* Wx     = (const float*)d_in[6];
    const float* Wh     = (const float*)d_in[7];
    const float* b_lstm = (const float*)d_in[8];
    float*       out    = (float*)d_out;

    attn_rnn_fused<<<B_, 256>>>(x, Wx, Wh, b_lstm, out);
}

// round 3
// speedup vs baseline: 1.7560x; 1.2516x over previous
#include <cuda_runtime.h>
#include <cuda_bf16.h>
#include <cstdint>
#include <math.h>

#define B_  128
#define F_  1024
#define W_  32
#define H_  64
#define G_  256
#define KC  16           // k (f) per chunk
#define NC  64           // F_/KC

#define AP  40           // A smem row pitch (bf16) for 32 t   (80B = 20 banks: conflict-free ldmatrix)
#define BP  264          // B smem row pitch (bf16) for 256 g  (528B = 132 banks: +4/row)

// per-stage offsets in bf16 units
#define OAH 0
#define OAL (KC*AP)               // 640
#define OBH (2*KC*AP)             // 1280
#define OBL (2*KC*AP + KC*BP)     // 5504
#define STG (2*KC*AP + 2*KC*BP)   // 9728 bf16 = 19456 B / stage

using u64 = unsigned long long;

// Pre-converted Wx in bf16 hi/lo (device globals per allocation rules; 1 MB)
__device__ __nv_bfloat16 g_wxh[F_ * G_];
__device__ __nv_bfloat16 g_wxl[F_ * G_];

__device__ __forceinline__ uint32_t smem_u32(const void* p) {
    return (uint32_t)__cvta_generic_to_shared(p);
}
__device__ __forceinline__ void cp16(uint32_t s, const void* g) {
    asm volatile("cp.async.cg.shared.global [%0], [%1], 16;" :: "r"(s), "l"(g));
}
__device__ __forceinline__ void ldm4t(uint32_t* r, uint32_t addr) {
    asm volatile("ldmatrix.sync.aligned.m8n8.x4.trans.shared.b16 {%0,%1,%2,%3}, [%4];"
                 : "=r"(r[0]), "=r"(r[1]), "=r"(r[2]), "=r"(r[3]) : "r"(addr));
}
__device__ __forceinline__ void mma_bf16(float* d, const uint32_t* a, uint32_t b0, uint32_t b1) {
    asm volatile("mma.sync.aligned.m16n8k16.row.col.f32.bf16.bf16.f32 "
                 "{%0,%1,%2,%3}, {%4,%5,%6,%7}, {%8,%9}, {%0,%1,%2,%3};"
                 : "+f"(d[0]), "+f"(d[1]), "+f"(d[2]), "+f"(d[3])
                 : "r"(a[0]), "r"(a[1]), "r"(a[2]), "r"(a[3]), "r"(b0), "r"(b1));
}
__device__ __forceinline__ u64 fma2(u64 a, u64 b, u64 c) {
    u64 d; asm("fma.rn.f32x2 %0, %1, %2, %3;" : "=l"(d) : "l"(a), "l"(b), "l"(c)); return d;
}
__device__ __forceinline__ u64 add2(u64 a, u64 b) {
    u64 d; asm("add.rn.f32x2 %0, %1, %2;" : "=l"(d) : "l"(a), "l"(b)); return d;
}
__device__ __forceinline__ u64 pack2(float lo, float hi) {
    u64 d; asm("mov.b64 %0, {%1, %2};" : "=l"(d)
               : "r"(__float_as_uint(lo)), "r"(__float_as_uint(hi)));
    return d;
}
__device__ __forceinline__ float2 unpack2(u64 a) {
    unsigned lo, hi; asm("mov.b64 {%0, %1}, %2;" : "=r"(lo), "=r"(hi) : "l"(a));
    return make_float2(__uint_as_float(lo), __uint_as_float(hi));
}

// ---------------------------------------------------------------------------
// Pre-kernel: Wx fp32 -> bf16 hi/lo split (runs every call; deterministic).
// ---------------------------------------------------------------------------
extern "C" __global__ void __launch_bounds__(256)
conv_wx_kernel(const float* __restrict__ Wx)
{
    int i = (blockIdx.x * 256 + threadIdx.x) * 4;
    float4 v = *(const float4*)(Wx + i);
    __nv_bfloat16 h[4], l[4];
    float f[4] = {v.x, v.y, v.z, v.w};
#pragma unroll
    for (int k = 0; k < 4; ++k) {
        h[k] = __float2bfloat16(f[k]);
        l[k] = __float2bfloat16(f[k] - __bfloat162float(h[k]));
    }
    *(uint2*)(g_wxh + i) = *(uint2*)h;
    *(uint2*)(g_wxl + i) = *(uint2*)l;
}

// ---------------------------------------------------------------------------
// Fused kernel: 1 block per batch, 256 threads.
//  Phase 1: Xp[t,g] = sum_f x[b,f,t]*Wx[f,g] via bf16 split-3 HMMA.
//    (softmax over the size-1 axis == 1, so the attention branch is dead code)
//    Warp w owns m32 x n32 (n0 = 32w). A tile from x is t-contiguous; stored
//    [k][t] -> ldmatrix.trans gives row-major m16k16 frags. B from
//    pre-split Wx via cp.async, stored [k][n] -> ldmatrix.trans = col-major.
//  Phase 2: LSTM recurrence (unchanged from R2; output = CELL state).
// ---------------------------------------------------------------------------
extern "C" __global__ void __launch_bounds__(256, 1)
attn_rnn_tc(const float* __restrict__ x,  const float* __restrict__ Wh,
            const float* __restrict__ b_lstm, float* __restrict__ out)
{
    __shared__ __align__(16) __nv_bfloat16 stg[2 * STG];   // 38912 B (reused as 32KB gate tile)
    __shared__ __align__(16) float h_s[2][H_];

    const int b    = blockIdx.x;
    const int tid  = threadIdx.x;
    const int w    = tid >> 5;
    const int lane = tid & 31;

    const float* xb = x + (size_t)b * F_ * W_;

    float acc[2][4][4];
#pragma unroll
    for (int mt = 0; mt < 2; ++mt)
#pragma unroll
        for (int j = 0; j < 4; ++j)
#pragma unroll
            for (int i = 0; i < 4; ++i) acc[mt][j][i] = 0.f;

    // ---- loaders ----
    float2 apf;                                  // A prefetch regs
    auto loadA = [&](int c) { apf = *(const float2*)(xb + c * KC * W_ + tid * 2); };
    auto stA = [&](int s) {
        int k = tid >> 4, t = (tid & 15) * 2;
        __nv_bfloat16 h0 = __float2bfloat16(apf.x);
        __nv_bfloat16 h1 = __float2bfloat16(apf.y);
        __nv_bfloat16 l0 = __float2bfloat16(apf.x - __bfloat162float(h0));
        __nv_bfloat16 l1 = __float2bfloat16(apf.y - __bfloat162float(h1));
        __nv_bfloat162* ah = (__nv_bfloat162*)(stg + s * STG + OAH + k * AP + t);
        __nv_bfloat162* al = (__nv_bfloat162*)(stg + s * STG + OAL + k * AP + t);
        *ah = __nv_bfloat162{h0, h1};
        *al = __nv_bfloat162{l0, l1};
    };
    auto loadB = [&](int c, int s) {
        __nv_bfloat16* bh = stg + s * STG + OBH;
        __nv_bfloat16* bl = stg + s * STG + OBL;
        const __nv_bfloat16* sH = g_wxh + c * KC * G_;
        const __nv_bfloat16* sL = g_wxl + c * KC * G_;
#pragma unroll
        for (int r = 0; r < 2; ++r) {
            int cid = tid + 256 * r;             // 0..511 -> 16 rows x 32 16B-chunks
            int row = cid >> 5, o = (cid & 31) * 8;
            cp16(smem_u32(bh + row * BP + o), sH + row * G_ + o);
            cp16(smem_u32(bl + row * BP + o), sL + row * G_ + o);
        }
    };

    // ldmatrix lane addressing
    const int lr = lane & 7, lg = lane >> 3;
    const int ak = (lg & 2) ? (8 + lr) : lr;     // A quadrants: (m0,k0)(m8,k0)(m0,k8)(m8,k8)
    const int amo = (lg & 1) ? 8 : 0;
    const int bk = (lg & 1) ? (8 + lr) : lr;     // B quadrants: (k0,n0)(k8,n0)(k0,n8)(k8,n8)
    const int bno = (lg & 2) ? 8 : 0;

    auto compute = [&](int s) {
        const __nv_bfloat16* base = stg + s * STG;
        uint32_t ah[2][4], al[2][4];
#pragma unroll
        for (int mt = 0; mt < 2; ++mt) {
            ldm4t(ah[mt], smem_u32(base + OAH + ak * AP + 16 * mt + amo));
            ldm4t(al[mt], smem_u32(base + OAL + ak * AP + 16 * mt + amo));
        }
#pragma unroll
        for (int jj = 0; jj < 2; ++jj) {
            int n0 = 32 * w + 16 * jj;
            uint32_t bh[4], bl[4];
            ldm4t(bh, smem_u32(base + OBH + bk * BP + n0 + bno));
            ldm4t(bl, smem_u32(base + OBL + bk * BP + n0 + bno));
#pragma unroll
            for (int mt = 0; mt < 2; ++mt) {
                mma_bf16(acc[mt][2 * jj],     ah[mt], bh[0], bh[1]);
                mma_bf16(acc[mt][2 * jj],     ah[mt], bl[0], bl[1]);
                mma_bf16(acc[mt][2 * jj],     al[mt], bh[0], bh[1]);
                mma_bf16(acc[mt][2 * jj + 1], ah[mt], bh[2], bh[3]);
                mma_bf16(acc[mt][2 * jj + 1], ah[mt], bl[2], bl[3]);
                mma_bf16(acc[mt][2 * jj + 1], al[mt], bh[2], bh[3]);
            }
        }
    };

    // ---- pipeline ----
    loadA(0); loadB(0, 0);
    asm volatile("cp.async.commit_group;");
    stA(0);
    asm volatile("cp.async.wait_group 0;");
    __syncthreads();

    for (int c = 0; c < NC; ++c) {
        if (c + 1 < NC) {
            loadA(c + 1);
            loadB(c + 1, (c + 1) & 1);
            asm volatile("cp.async.commit_group;");
        }
        compute(c & 1);
        if (c + 1 < NC) {
            stA((c + 1) & 1);
            asm volatile("cp.async.wait_group 0;");
        }
        __syncthreads();
    }

    // ---- epilogue: fragments -> gate tile [32][256] fp32 (reuses stage smem) ----
    float* xp = (float*)stg;
    const int r0 = lane >> 2, c0 = 2 * (lane & 3);
#pragma unroll
    for (int mt = 0; mt < 2; ++mt)
#pragma unroll
        for (int j = 0; j < 4; ++j) {
            int n = 32 * w + 8 * j;
            *(float2*)(xp + (16 * mt + r0) * G_ + n + c0)     = make_float2(acc[mt][j][0], acc[mt][j][1]);
            *(float2*)(xp + (16 * mt + r0 + 8) * G_ + n + c0) = make_float2(acc[mt][j][2], acc[mt][j][3]);
        }
    __syncthreads();

    // ---------------- Phase 2: LSTM recurrence ----------------
    const int q   = lane >> 3;
    const int r   = lane & 7;
    const int idx = 8 * w + r;
    const int col = q * 64 + idx;

    u64 whp[H_ / 2];
#pragma unroll
    for (int m = 0; m < H_ / 2; ++m)
        whp[m] = pack2(Wh[(2 * m) * G_ + col], Wh[(2 * m + 1) * G_ + col]);
    const float bj = b_lstm[col];

    if (tid < H_) h_s[0][tid] = 0.f;
    float c_st = 0.f;
    float* ob = out + (size_t)b * W_ * H_;
    __syncthreads();

    int p = 0;
    for (int t = 0; t < W_; ++t) {
        const u64* hp = (const u64*)h_s[p];
        u64 a0 = 0ull, a1 = 0ull, a2 = 0ull, a3 = 0ull;
#pragma unroll
        for (int m = 0; m < H_ / 2; m += 4) {
            a0 = fma2(hp[m + 0], whp[m + 0], a0);
            a1 = fma2(hp[m + 1], whp[m + 1], a1);
            a2 = fma2(hp[m + 2], whp[m + 2], a2);
            a3 = fma2(hp[m + 3], whp[m + 3], a3);
        }
        float2 s2 = unpack2(add2(add2(a0, a1), add2(a2, a3)));
        float g = s2.x + s2.y + xp[t * G_ + col] + bj;

        float sc  = (q == 2) ? -2.f : -1.f;
        float e   = __expf(sc * g);
        float num = (q == 2) ? (1.f - e) : 1.f;
        float act = __fdividef(num, 1.f + e);

        float ai = __shfl_sync(0xffffffffu, act, r);
        float af = __shfl_sync(0xffffffffu, act, 8 + r);
        float ag = __shfl_sync(0xffffffffu, act, 16 + r);
        float ao = __shfl_sync(0xffffffffu, act, 24 + r);

        c_st = fmaf(af, c_st, ai * ag);
        float e2 = __expf(-2.f * c_st);
        float th = __fdividef(1.f - e2, 1.f + e2);

        if (q == 0) {
            h_s[p ^ 1][idx] = ao * th;
            ob[t * H_ + idx] = c_st;              // reference emits the CELL state
        }
        p ^= 1;
        __syncthreads();
    }
}

// ---------------------------------------------------------------------------
extern "C" void kernel_launch(void* const* d_in, const int* in_sizes, int n_in,
                              void* d_out, int out_size)
{
    const float* x      = (const float*)d_in[0];
    const float* Wx     = (const float*)d_in[6];
    const float* Wh     = (const float*)d_in[7];
    const float* b_lstm = (const float*)d_in[8];
    float*       out    = (float*)d_out;

    conv_wx_kernel<<<F_ * G_ / 1024, 256>>>(Wx);
    attn_rnn_tc<<<B_, 256>>>(x, Wh, b_lstm, out);
}

// round 4
// speedup vs baseline: 1.8942x; 1.0787x over previous
#include <cuda_runtime.h>
#include <cuda_bf16.h>
#include <cstdint>
#include <math.h>

#define B_  128
#define F_  1024
#define W_  32
#define H_  64
#define G_  256
#define KR  32           // k rows per stage (16 per k-half)
#define NIT 32           // iterations (each k-half covers 512 = 32*16)

#define AP  40           // A smem row pitch (bf16): conflict-free ldmatrix
#define BP  264          // B smem row pitch (bf16)

// per-stage offsets in bf16 units
#define OAH 0
#define OAL (KR*AP)               // 1280
#define OBH (2*KR*AP)             // 2560
#define OBL (2*KR*AP + KR*BP)     // 11008
#define STG (2*KR*AP + 2*KR*BP)   // 19456 bf16 = 38912 B / stage
#define SMEM_DYN (2 * STG * 2)    // 77824 B

using u64 = unsigned long long;

// Pre-converted Wx in bf16 hi/lo (device globals per allocation rules; 1 MB)
__device__ __nv_bfloat16 g_wxh[F_ * G_];
__device__ __nv_bfloat16 g_wxl[F_ * G_];

__device__ __forceinline__ uint32_t smem_u32(const void* p) {
    return (uint32_t)__cvta_generic_to_shared(p);
}
__device__ __forceinline__ void cp16(uint32_t s, const void* g) {
    asm volatile("cp.async.cg.shared.global [%0], [%1], 16;" :: "r"(s), "l"(g));
}
__device__ __forceinline__ void ldm4t(uint32_t* r, uint32_t addr) {
    asm volatile("ldmatrix.sync.aligned.m8n8.x4.trans.shared.b16 {%0,%1,%2,%3}, [%4];"
                 : "=r"(r[0]), "=r"(r[1]), "=r"(r[2]), "=r"(r[3]) : "r"(addr));
}
__device__ __forceinline__ void mma_bf16(float* d, const uint32_t* a, uint32_t b0, uint32_t b1) {
    asm volatile("mma.sync.aligned.m16n8k16.row.col.f32.bf16.bf16.f32 "
                 "{%0,%1,%2,%3}, {%4,%5,%6,%7}, {%8,%9}, {%0,%1,%2,%3};"
                 : "+f"(d[0]), "+f"(d[1]), "+f"(d[2]), "+f"(d[3])
                 : "r"(a[0]), "r"(a[1]), "r"(a[2]), "r"(a[3]), "r"(b0), "r"(b1));
}
__device__ __forceinline__ u64 fma2(u64 a, u64 b, u64 c) {
    u64 d; asm("fma.rn.f32x2 %0, %1, %2, %3;" : "=l"(d) : "l"(a), "l"(b), "l"(c)); return d;
}
__device__ __forceinline__ u64 add2(u64 a, u64 b) {
    u64 d; asm("add.rn.f32x2 %0, %1, %2;" : "=l"(d) : "l"(a), "l"(b)); return d;
}
__device__ __forceinline__ u64 pack2(float lo, float hi) {
    u64 d; asm("mov.b64 %0, {%1, %2};" : "=l"(d)
               : "r"(__float_as_uint(lo)), "r"(__float_as_uint(hi)));
    return d;
}
__device__ __forceinline__ float2 unpack2(u64 a) {
    unsigned lo, hi; asm("mov.b64 {%0, %1}, %2;" : "=r"(lo), "=r"(hi) : "l"(a));
    return make_float2(__uint_as_float(lo), __uint_as_float(hi));
}

// ---------------------------------------------------------------------------
// Pre-kernel: Wx fp32 -> bf16 hi/lo split.
// ---------------------------------------------------------------------------
extern "C" __global__ void __launch_bounds__(256)
conv_wx_kernel(const float* __restrict__ Wx)
{
    int i = (blockIdx.x * 256 + threadIdx.x) * 4;
    float4 v = *(const float4*)(Wx + i);
    __nv_bfloat16 h[4], l[4];
    float f[4] = {v.x, v.y, v.z, v.w};
#pragma unroll
    for (int k = 0; k < 4; ++k) {
        h[k] = __float2bfloat16(f[k]);
        l[k] = __float2bfloat16(f[k] - __bfloat162float(h[k]));
    }
    *(uint2*)(g_wxh + i) = *(uint2*)h;
    *(uint2*)(g_wxl + i) = *(uint2*)l;
}

// ---------------------------------------------------------------------------
// Fused kernel: 1 block per batch, 512 threads (16 warps).
//  Phase 1: Xp[t,g] = sum_f x[b,f,t]*Wx[f,g], bf16 split-3 HMMA.
//   (softmax over the size-1 axis == 1 -> attention branch is dead code)
//   Warp (kg = w>>3, wn = w&7): m32 x n32 tile at n0=32*wn, k-half kg.
//   Stage holds a 32-row k-slab: rows [0,16) = f in [16c,16c+16),
//   rows [16,32) = f in [512+16c, 512+16c+16). Split-K-2 smem reduction.
//  Phase 2: LSTM recurrence on warps 0-7 (output = CELL state).
// ---------------------------------------------------------------------------
extern "C" __global__ void __launch_bounds__(512, 1)
attn_rnn_tc(const float* __restrict__ x,  const float* __restrict__ Wh,
            const float* __restrict__ b_lstm, float* __restrict__ out)
{
    extern __shared__ __align__(16) __nv_bfloat16 stg[];   // 2 stages; reused as gate tile
    __shared__ __align__(16) float h_s[2][H_];

    const int b    = blockIdx.x;
    const int tid  = threadIdx.x;
    const int w    = tid >> 5;
    const int lane = tid & 31;
    const int kg   = w >> 3;      // k-half
    const int wn   = w & 7;       // n-group

    const float* xb = x + (size_t)b * F_ * W_;

    float acc[2][4][4];
#pragma unroll
    for (int mt = 0; mt < 2; ++mt)
#pragma unroll
        for (int j = 0; j < 4; ++j)
#pragma unroll
            for (int i = 0; i < 4; ++i) acc[mt][j][i] = 0.f;

    // ---- loaders ----
    const int arow = tid >> 4;                   // 0..31 stage row
    const int af   = (arow < 16) ? arow : (512 - 16 + arow);   // +16c later
    float2 apf;
    auto loadA = [&](int c) { apf = *(const float2*)(xb + (size_t)(af + c * 16) * W_ + (tid & 15) * 2); };
    auto stA = [&](int s) {
        int t = (tid & 15) * 2;
        __nv_bfloat16 h0 = __float2bfloat16(apf.x);
        __nv_bfloat16 h1 = __float2bfloat16(apf.y);
        __nv_bfloat16 l0 = __float2bfloat16(apf.x - __bfloat162float(h0));
        __nv_bfloat16 l1 = __float2bfloat16(apf.y - __bfloat162float(h1));
        *(__nv_bfloat162*)(stg + s * STG + OAH + arow * AP + t) = __nv_bfloat162{h0, h1};
        *(__nv_bfloat162*)(stg + s * STG + OAL + arow * AP + t) = __nv_bfloat162{l0, l1};
    };
    auto loadB = [&](int c, int s) {
        __nv_bfloat16* bh = stg + s * STG + OBH;
        __nv_bfloat16* bl = stg + s * STG + OBL;
#pragma unroll
        for (int r = 0; r < 2; ++r) {
            int cid = tid + 512 * r;             // 0..1023 -> 32 rows x 32 16B-chunks
            int row = cid >> 5, o = (cid & 31) * 8;
            int f   = ((row < 16) ? row : (512 - 16 + row)) + c * 16;
            cp16(smem_u32(bh + row * BP + o), g_wxh + (size_t)f * G_ + o);
            cp16(smem_u32(bl + row * BP + o), g_wxl + (size_t)f * G_ + o);
        }
    };

    // ldmatrix lane addressing
    const int lr = lane & 7, lg = lane >> 3;
    const int ak  = ((lg & 2) ? (8 + lr) : lr) + kg * 16;
    const int amo = (lg & 1) ? 8 : 0;
    const int bk  = ((lg & 1) ? (8 + lr) : lr) + kg * 16;
    const int bno = (lg & 2) ? 8 : 0;

    auto compute = [&](int s) {
        const __nv_bfloat16* base = stg + s * STG;
        uint32_t ah[2][4], al[2][4];
#pragma unroll
        for (int mt = 0; mt < 2; ++mt) {
            ldm4t(ah[mt], smem_u32(base + OAH + ak * AP + 16 * mt + amo));
            ldm4t(al[mt], smem_u32(base + OAL + ak * AP + 16 * mt + amo));
        }
#pragma unroll
        for (int jj = 0; jj < 2; ++jj) {
            int n0 = 32 * wn + 16 * jj;
            uint32_t bh[4], bl[4];
            ldm4t(bh, smem_u32(base + OBH + bk * BP + n0 + bno));
            ldm4t(bl, smem_u32(base + OBL + bk * BP + n0 + bno));
#pragma unroll
            for (int mt = 0; mt < 2; ++mt) {
                mma_bf16(acc[mt][2 * jj],     ah[mt], bh[0], bh[1]);
                mma_bf16(acc[mt][2 * jj],     ah[mt], bl[0], bl[1]);
                mma_bf16(acc[mt][2 * jj],     al[mt], bh[0], bh[1]);
                mma_bf16(acc[mt][2 * jj + 1], ah[mt], bh[2], bh[3]);
                mma_bf16(acc[mt][2 * jj + 1], ah[mt], bl[2], bl[3]);
                mma_bf16(acc[mt][2 * jj + 1], al[mt], bh[2], bh[3]);
            }
        }
    };

    // ---- pipeline ----
    loadA(0); loadB(0, 0);
    asm volatile("cp.async.commit_group;");
    stA(0);
    asm volatile("cp.async.wait_group 0;");
    __syncthreads();

    for (int c = 0; c < NIT; ++c) {
        if (c + 1 < NIT) {
            loadA(c + 1);
            loadB(c + 1, (c + 1) & 1);
            asm volatile("cp.async.commit_group;");
        }
        compute(c & 1);
        if (c + 1 < NIT) {
            stA((c + 1) & 1);
            asm volatile("cp.async.wait_group 0;");
        }
        __syncthreads();
    }

    // ---- split-K-2 reduction into gate tile [32][256] fp32 ----
    float* xp = (float*)stg;
    const int r0 = lane >> 2, c0 = 2 * (lane & 3);
    if (kg == 1) {
#pragma unroll
        for (int mt = 0; mt < 2; ++mt)
#pragma unroll
            for (int j = 0; j < 4; ++j) {
                int n = 32 * wn + 8 * j;
                *(float2*)(xp + (16 * mt + r0) * G_ + n + c0)     = make_float2(acc[mt][j][0], acc[mt][j][1]);
                *(float2*)(xp + (16 * mt + r0 + 8) * G_ + n + c0) = make_float2(acc[mt][j][2], acc[mt][j][3]);
            }
    }
    __syncthreads();
    if (kg == 0) {
#pragma unroll
        for (int mt = 0; mt < 2; ++mt)
#pragma unroll
            for (int j = 0; j < 4; ++j) {
                int n = 32 * wn + 8 * j;
                float2* p0 = (float2*)(xp + (16 * mt + r0) * G_ + n + c0);
                float2* p1 = (float2*)(xp + (16 * mt + r0 + 8) * G_ + n + c0);
                float2 v0 = *p0, v1 = *p1;
                *p0 = make_float2(v0.x + acc[mt][j][0], v0.y + acc[mt][j][1]);
                *p1 = make_float2(v1.x + acc[mt][j][2], v1.y + acc[mt][j][3]);
            }
    }
    __syncthreads();

    // ---------------- Phase 2: LSTM recurrence (warps 0-7) ----------------
    const int q   = lane >> 3;
    const int r   = lane & 7;
    const int idx = 8 * (w & 7) + r;
    const int col = q * 64 + idx;

    u64 whp[H_ / 2];
    float bj = 0.f;
    if (tid < 256) {
#pragma unroll
        for (int m = 0; m < H_ / 2; ++m)
            whp[m] = pack2(Wh[(2 * m) * G_ + col], Wh[(2 * m + 1) * G_ + col]);
        bj = b_lstm[col];
    }

    if (tid < H_) h_s[0][tid] = 0.f;
    float c_st = 0.f;
    float* ob = out + (size_t)b * W_ * H_;
    __syncthreads();

    int p = 0;
    for (int t = 0; t < W_; ++t) {
        if (tid < 256) {
            const u64* hp = (const u64*)h_s[p];
            u64 a0 = 0ull, a1 = 0ull, a2 = 0ull, a3 = 0ull;
#pragma unroll
            for (int m = 0; m < H_ / 2; m += 4) {
                a0 = fma2(hp[m + 0], whp[m + 0], a0);
                a1 = fma2(hp[m + 1], whp[m + 1], a1);
                a2 = fma2(hp[m + 2], whp[m + 2], a2);
                a3 = fma2(hp[m + 3], whp[m + 3], a3);
            }
            float2 s2 = unpack2(add2(add2(a0, a1), add2(a2, a3)));
            float g = s2.x + s2.y + xp[t * G_ + col] + bj;

            float sc  = (q == 2) ? -2.f : -1.f;
            float e   = __expf(sc * g);
            float num = (q == 2) ? (1.f - e) : 1.f;
            float act = __fdividef(num, 1.f + e);

            float ai = __shfl_sync(0xffffffffu, act, r);
            float af = __shfl_sync(0xffffffffu, act, 8 + r);
            float ag = __shfl_sync(0xffffffffu, act, 16 + r);
            float ao = __shfl_sync(0xffffffffu, act, 24 + r);

            c_st = fmaf(af, c_st, ai * ag);
            float e2 = __expf(-2.f * c_st);
            float th = __fdividef(1.f - e2, 1.f + e2);

            if (q == 0) {
                h_s[p ^ 1][idx] = ao * th;
                ob[t * H_ + idx] = c_st;          // reference emits the CELL state
            }
        }
        p ^= 1;
        __syncthreads();
    }
}

// ---------------------------------------------------------------------------
extern "C" void kernel_launch(void* const* d_in, const int* in_sizes, int n_in,
                              void* d_out, int out_size)
{
    const float* x      = (const float*)d_in[0];
    const float* Wx     = (const float*)d_in[6];
    const float* Wh     = (const float*)d_in[7];
    const float* b_lstm = (const float*)d_in[8];
    float*       out    = (float*)d_out;

    cudaFuncSetAttribute(attn_rnn_tc, cudaFuncAttributeMaxDynamicSharedMemorySize, SMEM_DYN);

    conv_wx_kernel<<<F_ * G_ / 1024, 256>>>(Wx);
    attn_rnn_tc<<<B_, 512, SMEM_DYN>>>(x, Wh, b_lstm, out);
}

// round 5
// speedup vs baseline: 1.9607x; 1.0351x over previous
#include <cuda_runtime.h>
#include <cuda_bf16.h>
#include <cstdint>
#include <math.h>

#define B_  128
#define F_  1024
#define W_  32
#define H_  64
#define G_  256
#define KR  32           // k rows per stage (16 per k-half)
#define NIT 32           // iterations (each k-half covers 512 = 32*16)
#define NST 3            // pipeline stages

#define AP  40           // A smem row pitch (bf16): conflict-free ldmatrix
#define BP  264          // B smem row pitch (bf16)

// per-stage offsets in bf16 units
#define OAH 0
#define OAL (KR*AP)               // 1280
#define OBH (2*KR*AP)             // 2560
#define OBL (2*KR*AP + KR*BP)     // 11008
#define STG (2*KR*AP + 2*KR*BP)   // 19456 bf16 = 38912 B / stage
#define SMEM_DYN (NST * STG * 2)  // 116736 B

using u64 = unsigned long long;

// Pre-converted Wx in bf16 hi/lo (device globals per allocation rules; 1 MB)
__device__ __nv_bfloat16 g_wxh[F_ * G_];
__device__ __nv_bfloat16 g_wxl[F_ * G_];

__device__ __forceinline__ uint32_t smem_u32(const void* p) {
    return (uint32_t)__cvta_generic_to_shared(p);
}
__device__ __forceinline__ void cp16(uint32_t s, const void* g) {
    asm volatile("cp.async.cg.shared.global [%0], [%1], 16;" :: "r"(s), "l"(g));
}
__device__ __forceinline__ void ldm4t(uint32_t* r, uint32_t addr) {
    asm volatile("ldmatrix.sync.aligned.m8n8.x4.trans.shared.b16 {%0,%1,%2,%3}, [%4];"
                 : "=r"(r[0]), "=r"(r[1]), "=r"(r[2]), "=r"(r[3]) : "r"(addr));
}
__device__ __forceinline__ void mma_bf16(float* d, const uint32_t* a, uint32_t b0, uint32_t b1) {
    asm volatile("mma.sync.aligned.m16n8k16.row.col.f32.bf16.bf16.f32 "
                 "{%0,%1,%2,%3}, {%4,%5,%6,%7}, {%8,%9}, {%0,%1,%2,%3};"
                 : "+f"(d[0]), "+f"(d[1]), "+f"(d[2]), "+f"(d[3])
                 : "r"(a[0]), "r"(a[1]), "r"(a[2]), "r"(a[3]), "r"(b0), "r"(b1));
}
__device__ __forceinline__ u64 fma2(u64 a, u64 b, u64 c) {
    u64 d; asm("fma.rn.f32x2 %0, %1, %2, %3;" : "=l"(d) : "l"(a), "l"(b), "l"(c)); return d;
}
__device__ __forceinline__ u64 add2(u64 a, u64 b) {
    u64 d; asm("add.rn.f32x2 %0, %1, %2;" : "=l"(d) : "l"(a), "l"(b)); return d;
}
__device__ __forceinline__ u64 pack2(float lo, float hi) {
    u64 d; asm("mov.b64 %0, {%1, %2};" : "=l"(d)
               : "r"(__float_as_uint(lo)), "r"(__float_as_uint(hi)));
    return d;
}
__device__ __forceinline__ float2 unpack2(u64 a) {
    unsigned lo, hi; asm("mov.b64 {%0, %1}, %2;" : "=r"(lo), "=r"(hi) : "l"(a));
    return make_float2(__uint_as_float(lo), __uint_as_float(hi));
}
__device__ __forceinline__ void bar256() {
    asm volatile("bar.sync 1, 256;" ::: "memory");
}

// ---------------------------------------------------------------------------
// Pre-kernel: Wx fp32 -> bf16 hi/lo split.
// ---------------------------------------------------------------------------
extern "C" __global__ void __launch_bounds__(256)
conv_wx_kernel(const float* __restrict__ Wx)
{
    int i = (blockIdx.x * 256 + threadIdx.x) * 4;
    float4 v = *(const float4*)(Wx + i);
    __nv_bfloat16 h[4], l[4];
    float f[4] = {v.x, v.y, v.z, v.w};
#pragma unroll
    for (int k = 0; k < 4; ++k) {
        h[k] = __float2bfloat16(f[k]);
        l[k] = __float2bfloat16(f[k] - __bfloat162float(h[k]));
    }
    *(uint2*)(g_wxh + i) = *(uint2*)h;
    *(uint2*)(g_wxl + i) = *(uint2*)l;
}

// ---------------------------------------------------------------------------
// Fused kernel: 1 block per batch, 512 threads (16 warps).
//  Phase 1: Xp[t,g] = sum_f x[b,f,t]*Wx[f,g], bf16 split-3 HMMA.
//   (softmax over the size-1 axis == 1 -> attention branch is dead code)
//   3-stage cp.async pipeline, wait_group 1: L2 latency hidden under mma.
//   Warp (kg = w>>3, wn = w&7): m32 x n32 tile at n0=32*wn, k-half kg.
//  Phase 2: LSTM recurrence on warps 0-7 (named barrier); warps 8-15 exit.
//   Output per step = CELL state (reference's s/h swap).
// ---------------------------------------------------------------------------
extern "C" __global__ void __launch_bounds__(512, 1)
attn_rnn_tc(const float* __restrict__ x,  const float* __restrict__ Wh,
            const float* __restrict__ b_lstm, float* __restrict__ out)
{
    extern __shared__ __align__(16) __nv_bfloat16 stg[];   // 3 stages; reused as gate tile
    __shared__ __align__(16) float h_s[2][H_];

    const int b    = blockIdx.x;
    const int tid  = threadIdx.x;
    const int w    = tid >> 5;
    const int lane = tid & 31;
    const int kg   = w >> 3;      // k-half
    const int wn   = w & 7;       // n-group

    const float* xb = x + (size_t)b * F_ * W_;

    float acc[2][4][4];
#pragma unroll
    for (int mt = 0; mt < 2; ++mt)
#pragma unroll
        for (int j = 0; j < 4; ++j)
#pragma unroll
            for (int i = 0; i < 4; ++i) acc[mt][j][i] = 0.f;

    // ---- loaders ----
    const int arow = tid >> 4;                   // 0..31 stage row
    const int af   = (arow < 16) ? arow : (512 - 16 + arow);   // +16c later
    float2 apf;
    auto loadA = [&](int c) { apf = *(const float2*)(xb + (size_t)(af + c * 16) * W_ + (tid & 15) * 2); };
    auto stA = [&](int s) {
        int t = (tid & 15) * 2;
        __nv_bfloat16 h0 = __float2bfloat16(apf.x);
        __nv_bfloat16 h1 = __float2bfloat16(apf.y);
        __nv_bfloat16 l0 = __float2bfloat16(apf.x - __bfloat162float(h0));
        __nv_bfloat16 l1 = __float2bfloat16(apf.y - __bfloat162float(h1));
        *(__nv_bfloat162*)(stg + s * STG + OAH + arow * AP + t) = __nv_bfloat162{h0, h1};
        *(__nv_bfloat162*)(stg + s * STG + OAL + arow * AP + t) = __nv_bfloat162{l0, l1};
    };
    auto loadB = [&](int c, int s) {
        __nv_bfloat16* bh = stg + s * STG + OBH;
        __nv_bfloat16* bl = stg + s * STG + OBL;
#pragma unroll
        for (int r = 0; r < 2; ++r) {
            int cid = tid + 512 * r;             // 0..1023 -> 32 rows x 32 16B-chunks
            int row = cid >> 5, o = (cid & 31) * 8;
            int f   = ((row < 16) ? row : (512 - 16 + row)) + c * 16;
            cp16(smem_u32(bh + row * BP + o), g_wxh + (size_t)f * G_ + o);
            cp16(smem_u32(bl + row * BP + o), g_wxl + (size_t)f * G_ + o);
        }
    };

    // ldmatrix lane addressing
    const int lr = lane & 7, lg = lane >> 3;
    const int ak  = ((lg & 2) ? (8 + lr) : lr) + kg * 16;
    const int amo = (lg & 1) ? 8 : 0;
    const int bk  = ((lg & 1) ? (8 + lr) : lr) + kg * 16;
    const int bno = (lg & 2) ? 8 : 0;

    auto compute = [&](int s) {
        const __nv_bfloat16* base = stg + s * STG;
        uint32_t ah[2][4], al[2][4];
#pragma unroll
        for (int mt = 0; mt < 2; ++mt) {
            ldm4t(ah[mt], smem_u32(base + OAH + ak * AP + 16 * mt + amo));
            ldm4t(al[mt], smem_u32(base + OAL + ak * AP + 16 * mt + amo));
        }
#pragma unroll
        for (int jj = 0; jj < 2; ++jj) {
            int n0 = 32 * wn + 16 * jj;
            uint32_t bh[4], bl[4];
            ldm4t(bh, smem_u32(base + OBH + bk * BP + n0 + bno));
            ldm4t(bl, smem_u32(base + OBL + bk * BP + n0 + bno));
#pragma unroll
            for (int mt = 0; mt < 2; ++mt) {
                mma_bf16(acc[mt][2 * jj],     ah[mt], bh[0], bh[1]);
                mma_bf16(acc[mt][2 * jj],     ah[mt], bl[0], bl[1]);
                mma_bf16(acc[mt][2 * jj],     al[mt], bh[0], bh[1]);
                mma_bf16(acc[mt][2 * jj + 1], ah[mt], bh[2], bh[3]);
                mma_bf16(acc[mt][2 * jj + 1], ah[mt], bl[2], bl[3]);
                mma_bf16(acc[mt][2 * jj + 1], al[mt], bh[2], bh[3]);
            }
        }
    };

    // ---- 3-stage pipeline ----
    loadA(0); loadB(0, 0);
    asm volatile("cp.async.commit_group;");
    stA(0);
    loadA(1); loadB(1, 1);
    asm volatile("cp.async.commit_group;");
    stA(1);
    asm volatile("cp.async.wait_group 1;");   // stage 0 ready
    __syncthreads();

    int s_cur = 0, s_nxt = 2;                  // compute stage, load target stage
    for (int c = 0; c < NIT; ++c) {
        compute(s_cur);
        if (c + 2 < NIT) {
            loadA(c + 2);
            loadB(c + 2, s_nxt);
            asm volatile("cp.async.commit_group;");
            stA(s_nxt);
            asm volatile("cp.async.wait_group 1;");   // stage c+1 ready
        } else {
            asm volatile("cp.async.wait_group 0;");
        }
        __syncthreads();
        s_cur = (s_cur == NST - 1) ? 0 : s_cur + 1;
        s_nxt = (s_nxt == NST - 1) ? 0 : s_nxt + 1;
    }

    // ---- split-K-2 reduction into gate tile [32][256] fp32 ----
    float* xp = (float*)stg;
    const int r0 = lane >> 2, c0 = 2 * (lane & 3);
    if (kg == 1) {
#pragma unroll
        for (int mt = 0; mt < 2; ++mt)
#pragma unroll
            for (int j = 0; j < 4; ++j) {
                int n = 32 * wn + 8 * j;
                *(float2*)(xp + (16 * mt + r0) * G_ + n + c0)     = make_float2(acc[mt][j][0], acc[mt][j][1]);
                *(float2*)(xp + (16 * mt + r0 + 8) * G_ + n + c0) = make_float2(acc[mt][j][2], acc[mt][j][3]);
            }
    }
    __syncthreads();
    if (kg == 0) {
#pragma unroll
        for (int mt = 0; mt < 2; ++mt)
#pragma unroll
            for (int j = 0; j < 4; ++j) {
                int n = 32 * wn + 8 * j;
                float2* p0 = (float2*)(xp + (16 * mt + r0) * G_ + n + c0);
                float2* p1 = (float2*)(xp + (16 * mt + r0 + 8) * G_ + n + c0);
                float2 v0 = *p0, v1 = *p1;
                *p0 = make_float2(v0.x + acc[mt][j][0], v0.y + acc[mt][j][1]);
                *p1 = make_float2(v1.x + acc[mt][j][2], v1.y + acc[mt][j][3]);
            }
    }
    __syncthreads();

    // ---------------- Phase 2: LSTM recurrence (warps 0-7 only) ----------------
    if (tid >= 256) return;                       // warps 8-15 done

    const int q   = lane >> 3;
    const int r   = lane & 7;
    const int idx = 8 * w + r;
    const int col = q * 64 + idx;

    u64 whp[H_ / 2];
#pragma unroll
    for (int m = 0; m < H_ / 2; ++m)
        whp[m] = pack2(Wh[(2 * m) * G_ + col], Wh[(2 * m + 1) * G_ + col]);
    const float bj = b_lstm[col];

    if (tid < H_) h_s[0][tid] = 0.f;
    float c_st = 0.f;
    float* ob = out + (size_t)b * W_ * H_;
    bar256();

    int p = 0;
    for (int t = 0; t < W_; ++t) {
        const u64* hp = (const u64*)h_s[p];
        u64 a0 = 0ull, a1 = 0ull, a2 = 0ull, a3 = 0ull;
#pragma unroll
        for (int m = 0; m < H_ / 2; m += 4) {
            a0 = fma2(hp[m + 0], whp[m + 0], a0);
            a1 = fma2(hp[m + 1], whp[m + 1], a1);
            a2 = fma2(hp[m + 2], whp[m + 2], a2);
            a3 = fma2(hp[m + 3], whp[m + 3], a3);
        }
        float2 s2 = unpack2(add2(add2(a0, a1), add2(a2, a3)));
        float g = s2.x + s2.y + xp[t * G_ + col] + bj;

        float sc  = (q == 2) ? -2.f : -1.f;
        float e   = __expf(sc * g);
        float num = (q == 2) ? (1.f - e) : 1.f;
        float act = __fdividef(num, 1.f + e);

        float ai = __shfl_sync(0xffffffffu, act, r);
        float af = __shfl_sync(0xffffffffu, act, 8 + r);
        float ag = __shfl_sync(0xffffffffu, act, 16 + r);
        float ao = __shfl_sync(0xffffffffu, act, 24 + r);

        c_st = fmaf(af, c_st, ai * ag);
        float e2 = __expf(-2.f * c_st);
        float th = __fdividef(1.f - e2, 1.f + e2);

        if (q == 0) {
            h_s[p ^ 1][idx] = ao * th;
            ob[t * H_ + idx] = c_st;              // reference emits the CELL state
        }
        p ^= 1;
        bar256();
    }
}

// ---------------------------------------------------------------------------
extern "C" void kernel_launch(void* const* d_in, const int* in_sizes, int n_in,
                              void* d_out, int out_size)
{
    const float* x      = (const float*)d_in[0];
    const float* Wx     = (const float*)d_in[6];
    const float* Wh     = (const float*)d_in[7];
    const float* b_lstm = (const float*)d_in[8];
    float*       out    = (float*)d_out;

    cudaFuncSetAttribute(attn_rnn_tc, cudaFuncAttributeMaxDynamicSharedMemorySize, SMEM_DYN);

    conv_wx_kernel<<<F_ * G_ / 1024, 256>>>(Wx);
    attn_rnn_tc<<<B_, 512, SMEM_DYN>>>(x, Wh, b_lstm, out);
}

// round 6
// speedup vs baseline: 2.4906x; 1.2703x over previous
#include <cuda_runtime.h>
#include <cuda_bf16.h>
#include <cstdint>
#include <math.h>

#define B_  128
#define F_  1024
#define W_  32
#define H_  64
#define G_  256
#define NCH 64           // total k16 chunks
#define NIT 32           // chunks per k-half (per warp)

#define AP  40           // A smem row pitch (bf16): conflict-free ldmatrix
#define OAL (F_ * AP)    // A-lo offset (bf16 units): 40960
#define SMEM_DYN (2 * F_ * AP * 2)   // 163840 B

using u64 = unsigned long long;

// B pre-packed into mma-fragment layout: [chunk][ntile][lane] -> uint4{bh0,bh1,bl0,bl1}
__device__ uint4 g_wxp[NCH * 32 * 32];

__device__ __forceinline__ uint32_t smem_u32(const void* p) {
    return (uint32_t)__cvta_generic_to_shared(p);
}
__device__ __forceinline__ void ldm4t(uint32_t* r, uint32_t addr) {
    asm volatile("ldmatrix.sync.aligned.m8n8.x4.trans.shared.b16 {%0,%1,%2,%3}, [%4];"
                 : "=r"(r[0]), "=r"(r[1]), "=r"(r[2]), "=r"(r[3]) : "r"(addr));
}
__device__ __forceinline__ void mma_bf16(float* d, const uint32_t* a, uint32_t b0, uint32_t b1) {
    asm volatile("mma.sync.aligned.m16n8k16.row.col.f32.bf16.bf16.f32 "
                 "{%0,%1,%2,%3}, {%4,%5,%6,%7}, {%8,%9}, {%0,%1,%2,%3};"
                 : "+f"(d[0]), "+f"(d[1]), "+f"(d[2]), "+f"(d[3])
                 : "r"(a[0]), "r"(a[1]), "r"(a[2]), "r"(a[3]), "r"(b0), "r"(b1));
}
__device__ __forceinline__ u64 fma2(u64 a, u64 b, u64 c) {
    u64 d; asm("fma.rn.f32x2 %0, %1, %2, %3;" : "=l"(d) : "l"(a), "l"(b), "l"(c)); return d;
}
__device__ __forceinline__ u64 add2(u64 a, u64 b) {
    u64 d; asm("add.rn.f32x2 %0, %1, %2;" : "=l"(d) : "l"(a), "l"(b)); return d;
}
__device__ __forceinline__ u64 pack2(float lo, float hi) {
    u64 d; asm("mov.b64 %0, {%1, %2};" : "=l"(d)
               : "r"(__float_as_uint(lo)), "r"(__float_as_uint(hi)));
    return d;
}
__device__ __forceinline__ float2 unpack2(u64 a) {
    unsigned lo, hi; asm("mov.b64 {%0, %1}, %2;" : "=r"(lo), "=r"(hi) : "l"(a));
    return make_float2(__uint_as_float(lo), __uint_as_float(hi));
}
__device__ __forceinline__ uint32_t packbf(float a, float b) {
    uint32_t r; asm("cvt.rn.bf16x2.f32 %0, %1, %2;" : "=r"(r) : "f"(b), "f"(a));
    return r;   // low half = a, high = b
}

// ---------------------------------------------------------------------------
// Pre-kernel: Wx fp32 -> packed bf16 hi/lo mma B-fragments.
// gid = (chunk*32 + ntile)*32 + lane ; n = ntile*8 + lane/4 ; k0 = chunk*16 + 2*(lane%4)
// b0 covers k0,k0+1 ; b1 covers k0+8,k0+9 (PTX m16n8k16 B layout).
// ---------------------------------------------------------------------------
extern "C" __global__ void __launch_bounds__(256)
conv_wx_kernel(const float* __restrict__ Wx)
{
    int gid   = blockIdx.x * 256 + threadIdx.x;       // 0..65535
    int lane  = gid & 31;
    int tile  = (gid >> 5) & 31;
    int chunk = gid >> 10;
    int n  = tile * 8 + (lane >> 2);
    int k0 = chunk * 16 + 2 * (lane & 3);

    float w00 = Wx[(size_t)k0 * G_ + n];
    float w01 = Wx[(size_t)(k0 + 1) * G_ + n];
    float w10 = Wx[(size_t)(k0 + 8) * G_ + n];
    float w11 = Wx[(size_t)(k0 + 9) * G_ + n];

    float h00 = __bfloat162float(__float2bfloat16(w00));
    float h01 = __bfloat162float(__float2bfloat16(w01));
    float h10 = __bfloat162float(__float2bfloat16(w10));
    float h11 = __bfloat162float(__float2bfloat16(w11));

    uint4 v;
    v.x = packbf(h00, h01);                  // bh0
    v.y = packbf(h10, h11);                  // bh1
    v.z = packbf(w00 - h00, w01 - h01);      // bl0
    v.w = packbf(w10 - h10, w11 - h11);      // bl1
    g_wxp[gid] = v;
}

// ---------------------------------------------------------------------------
// Fused kernel: 1 block per batch, 512 threads (16 warps).
//  Prologue: stage full A (x[b], hi/lo bf16) into smem once (160 KB).
//  Phase 1: barrier-free GEMM. Warp (kg=w>>3, wn=w&7) computes m32 x n32
//   (n0=32wn) over k-half kg. A frags via ldmatrix, B frags via direct
//   LDG.128 from the pre-packed fragment array (prefetched 1 chunk ahead).
//   Split-K-2 smem reduction into the gate tile (reuses A region).
//   (softmax over the size-1 axis == 1 -> attention branch is dead code)
//  Phase 2: LSTM recurrence on warps 0-7; output = CELL state.
// ---------------------------------------------------------------------------
extern "C" __global__ void __launch_bounds__(512, 1)
attn_rnn_tc(const float* __restrict__ x,  const float* __restrict__ Wh,
            const float* __restrict__ b_lstm, float* __restrict__ out)
{
    extern __shared__ __align__(16) __nv_bfloat16 stg[];   // AH[0..OAL) AL[OAL..) ; later gate tile
    __shared__ __align__(16) float h_s[2][H_];

    const int b    = blockIdx.x;
    const int tid  = threadIdx.x;
    const int w    = tid >> 5;
    const int lane = tid & 31;
    const int kg   = w >> 3;      // k-half
    const int wn   = w & 7;       // n-group

    const float* xb = x + (size_t)b * F_ * W_;

    // ---- Prologue: stage all of A (hi/lo) ----
    {
        const int rbase = tid >> 4;           // 0..31
        const int tc    = (tid & 15) * 2;     // t column pair
#pragma unroll 4
        for (int seg = 0; seg < 32; ++seg) {
            int f = rbase + 32 * seg;
            float2 v = *(const float2*)(xb + (size_t)f * W_ + tc);
            __nv_bfloat16 h0 = __float2bfloat16(v.x);
            __nv_bfloat16 h1 = __float2bfloat16(v.y);
            __nv_bfloat16 l0 = __float2bfloat16(v.x - __bfloat162float(h0));
            __nv_bfloat16 l1 = __float2bfloat16(v.y - __bfloat162float(h1));
            *(__nv_bfloat162*)(stg + f * AP + tc)       = __nv_bfloat162{h0, h1};
            *(__nv_bfloat162*)(stg + OAL + f * AP + tc) = __nv_bfloat162{l0, l1};
        }
    }
    __syncthreads();

    float acc[2][4][4];
#pragma unroll
    for (int mt = 0; mt < 2; ++mt)
#pragma unroll
        for (int j = 0; j < 4; ++j)
#pragma unroll
            for (int i = 0; i < 4; ++i) acc[mt][j][i] = 0.f;

    // ldmatrix lane addressing (within a chunk)
    const int lr = lane & 7, lg = lane >> 3;
    const int akq = (lg & 2) ? (8 + lr) : lr;
    const int amo = (lg & 1) ? 8 : 0;

    // B source: chunk-major; this warp's 4 n-tiles start at tile 4*wn
    const uint4* bsrc = g_wxp + ((size_t)(4 * wn) * 32) + lane;
    const int ch0 = kg * NIT;

    uint4 bq[4], bq_n[4];
#pragma unroll
    for (int j = 0; j < 4; ++j)
        bq[j] = bsrc[(size_t)(ch0) * 1024 + (size_t)j * 32];

    for (int c = 0; c < NIT; ++c) {
        int cn = (c + 1 < NIT) ? (ch0 + c + 1) : (ch0 + c);   // clamp last prefetch
#pragma unroll
        for (int j = 0; j < 4; ++j)
            bq_n[j] = bsrc[(size_t)cn * 1024 + (size_t)j * 32];

        int fb = (ch0 + c) * 16 + akq;
        uint32_t ah[2][4], al[2][4];
#pragma unroll
        for (int mt = 0; mt < 2; ++mt) {
            ldm4t(ah[mt], smem_u32(stg + fb * AP + 16 * mt + amo));
            ldm4t(al[mt], smem_u32(stg + OAL + fb * AP + 16 * mt + amo));
        }
#pragma unroll
        for (int j = 0; j < 4; ++j) {
#pragma unroll
            for (int mt = 0; mt < 2; ++mt) {
                mma_bf16(acc[mt][j], ah[mt], bq[j].x, bq[j].y);   // ah*bh
                mma_bf16(acc[mt][j], ah[mt], bq[j].z, bq[j].w);   // ah*bl
                mma_bf16(acc[mt][j], al[mt], bq[j].x, bq[j].y);   // al*bh
            }
        }
#pragma unroll
        for (int j = 0; j < 4; ++j) bq[j] = bq_n[j];
    }
    __syncthreads();     // all warps done reading A before gate tile overwrites it

    // ---- split-K-2 reduction into gate tile [32][256] fp32 ----
    float* xp = (float*)stg;
    const int r0 = lane >> 2, c0 = 2 * (lane & 3);
    if (kg == 1) {
#pragma unroll
        for (int mt = 0; mt < 2; ++mt)
#pragma unroll
            for (int j = 0; j < 4; ++j) {
                int n = 32 * wn + 8 * j;
                *(float2*)(xp + (16 * mt + r0) * G_ + n + c0)     = make_float2(acc[mt][j][0], acc[mt][j][1]);
                *(float2*)(xp + (16 * mt + r0 + 8) * G_ + n + c0) = make_float2(acc[mt][j][2], acc[mt][j][3]);
            }
    }
    __syncthreads();
    if (kg == 0) {
#pragma unroll
        for (int mt = 0; mt < 2; ++mt)
#pragma unroll
            for (int j = 0; j < 4; ++j) {
                int n = 32 * wn + 8 * j;
                float2* p0 = (float2*)(xp + (16 * mt + r0) * G_ + n + c0);
                float2* p1 = (float2*)(xp + (16 * mt + r0 + 8) * G_ + n + c0);
                float2 v0 = *p0, v1 = *p1;
                *p0 = make_float2(v0.x + acc[mt][j][0], v0.y + acc[mt][j][1]);
                *p1 = make_float2(v1.x + acc[mt][j][2], v1.y + acc[mt][j][3]);
            }
    }
    __syncthreads();

    // ---------------- Phase 2: LSTM recurrence (warps 0-7 only) ----------------
    if (tid >= 256) return;

    const int q   = lane >> 3;
    const int r   = lane & 7;
    const int idx = 8 * w + r;
    const int col = q * 64 + idx;

    u64 whp[H_ / 2];
#pragma unroll
    for (int m = 0; m < H_ / 2; ++m)
        whp[m] = pack2(Wh[(2 * m) * G_ + col], Wh[(2 * m + 1) * G_ + col]);
    const float bj = b_lstm[col];

    if (tid < H_) h_s[0][tid] = 0.f;
    float c_st = 0.f;
    float* ob = out + (size_t)b * W_ * H_;
    asm volatile("bar.sync 1, 256;" ::: "memory");

    int p = 0;
    for (int t = 0; t < W_; ++t) {
        const u64* hp = (const u64*)h_s[p];
        u64 a0 = 0ull, a1 = 0ull, a2 = 0ull, a3 = 0ull;
#pragma unroll
        for (int m = 0; m < H_ / 2; m += 4) {
            a0 = fma2(hp[m + 0], whp[m + 0], a0);
            a1 = fma2(hp[m + 1], whp[m + 1], a1);
            a2 = fma2(hp[m + 2], whp[m + 2], a2);
            a3 = fma2(hp[m + 3], whp[m + 3], a3);
        }
        float2 s2 = unpack2(add2(add2(a0, a1), add2(a2, a3)));
        float g = s2.x + s2.y + xp[t * G_ + col] + bj;

        float sc  = (q == 2) ? -2.f : -1.f;
        float e   = __expf(sc * g);
        float num = (q == 2) ? (1.f - e) : 1.f;
        float act = __fdividef(num, 1.f + e);

        float ai = __shfl_sync(0xffffffffu, act, r);
        float af = __shfl_sync(0xffffffffu, act, 8 + r);
        float ag = __shfl_sync(0xffffffffu, act, 16 + r);
        float ao = __shfl_sync(0xffffffffu, act, 24 + r);

        c_st = fmaf(af, c_st, ai * ag);
        float e2 = __expf(-2.f * c_st);
        float th = __fdividef(1.f - e2, 1.f + e2);

        if (q == 0) {
            h_s[p ^ 1][idx] = ao * th;
            ob[t * H_ + idx] = c_st;              // reference emits the CELL state
        }
        p ^= 1;
        asm volatile("bar.sync 1, 256;" ::: "memory");
    }
}

// ---------------------------------------------------------------------------
extern "C" void kernel_launch(void* const* d_in, const int* in_sizes, int n_in,
                              void* d_out, int out_size)
{
    const float* x      = (const float*)d_in[0];
    const float* Wx     = (const float*)d_in[6];
    const float* Wh     = (const float*)d_in[7];
    const float* b_lstm = (const float*)d_in[8];
    float*       out    = (float*)d_out;

    cudaFuncSetAttribute(attn_rnn_tc, cudaFuncAttributeMaxDynamicSharedMemorySize, SMEM_DYN);

    conv_wx_kernel<<<256, 256>>>(Wx);
    attn_rnn_tc<<<B_, 512, SMEM_DYN>>>(x, Wh, b_lstm, out);
}